// round 15
// baseline (speedup 1.0000x reference)
#include <cuda_runtime.h>
#include <cuda_bf16.h>
#include <cuda_fp16.h>
#include <cstdint>

#define NN 200000
#define EE 6400000
#define BB 64
#define MM 8192
#define KK 2560

// -------- scratch (device globals; no allocation allowed) --------
__device__ uint4 g_xlh[NN];          // 6 fp16 + pad per node
__device__ uint4 g_xrh[NN];
__device__ uint4 g_aggh[NN];         // 8 fp16: [0..5]=sum p*xl, [6]=sum p, [7]=pad
__device__ float g_pooled[BB * 8];   // [0..3]=sum h, [4]=count
__device__ float g_f1[MM * 256];
__device__ float g_f2[MM * 64];
__device__ float g_f3[MM * 8];
__device__ float g_xf[BB * 32];

__device__ __forceinline__ float lrelu(float v, float s) { return v >= 0.f ? v : s * v; }

__device__ __forceinline__ void red_add_v4h(uint4* addr, uint32_t a, uint32_t b,
                                            uint32_t c, uint32_t d) {
    asm volatile("red.relaxed.gpu.global.add.noftz.v4.f16x2 [%0], {%1,%2,%3,%4};"
                 :: "l"(addr), "r"(a), "r"(b), "r"(c), "r"(d) : "memory");
}

__device__ __forceinline__ float ex2f(float x) {
    float r;
    asm("ex2.approx.f32 %0, %1;" : "=f"(r) : "f"(x));
    return r;
}

__device__ __forceinline__ uint32_t pack_bf16x2(float lo, float hi) {
    uint32_t r;
    asm("cvt.rn.bf16x2.f32 %0, %1, %2;" : "=r"(r) : "f"(hi), "f"(lo));
    return r;
}

__device__ __forceinline__ void mma_bf16(float (&c)[4], const uint32_t (&a)[4],
                                         const uint32_t (&b)[2]) {
    asm volatile(
        "mma.sync.aligned.m16n8k16.row.col.f32.bf16.bf16.f32 "
        "{%0,%1,%2,%3}, {%4,%5,%6,%7}, {%8,%9}, {%0,%1,%2,%3};"
        : "+f"(c[0]), "+f"(c[1]), "+f"(c[2]), "+f"(c[3])
        : "r"(a[0]), "r"(a[1]), "r"(a[2]), "r"(a[3]), "r"(b[0]), "r"(b[1]));
}

// -------- zero scratch --------
__global__ void k_zero() {
    int i = blockIdx.x * 256 + threadIdx.x;
    if (i < NN) g_aggh[i] = make_uint4(0u, 0u, 0u, 0u);
    if (i < BB * 2) *(float4*)&g_pooled[i * 4] = make_float4(0.f, 0.f, 0.f, 0.f);
}

// -------- xl = x@W_l + b_l, xr = x@W_r + b_r  (fp16-packed outputs) --------
__global__ void k_xlxr(const float* __restrict__ x, const float* __restrict__ Wl,
                       const float* __restrict__ Wr, const float* __restrict__ bl,
                       const float* __restrict__ br) {
    __shared__ float xs[16][516];
    __shared__ float sW[128][12];
    int tid = threadIdx.x;          // 128 threads
    for (int i = tid; i < 768; i += 128) {
        int k = i / 6, j = i % 6;
        sW[k][j]     = Wl[i];
        sW[k][j + 6] = Wr[i];
    }
    int base = blockIdx.x * 512;
    float acc[4][12];
#pragma unroll
    for (int i = 0; i < 4; i++)
#pragma unroll
        for (int j = 0; j < 12; j++) acc[i][j] = 0.f;
    int r0 = tid * 4;
    for (int kt = 0; kt < 8; kt++) {
        int k0 = kt * 16;
        __syncthreads();
#pragma unroll
        for (int it = 0; it < 16; it++) {
            int fid = it * 128 + tid;
            int r = fid >> 2;
            int c4 = (fid & 3) * 4;
            int row = base + r;
            float4 v = make_float4(0.f, 0.f, 0.f, 0.f);
            if (row < NN) v = *(const float4*)&x[row * 128 + k0 + c4];
            xs[c4 + 0][r] = v.x; xs[c4 + 1][r] = v.y;
            xs[c4 + 2][r] = v.z; xs[c4 + 3][r] = v.w;
        }
        __syncthreads();
#pragma unroll
        for (int k = 0; k < 16; k++) {
            float w[12];
#pragma unroll
            for (int j = 0; j < 12; j++) w[j] = sW[k0 + k][j];
            float4 xa = *(const float4*)&xs[k][r0];
            float xv[4] = {xa.x, xa.y, xa.z, xa.w};
#pragma unroll
            for (int i = 0; i < 4; i++)
#pragma unroll
                for (int j = 0; j < 12; j++) acc[i][j] += xv[i] * w[j];
        }
    }
#pragma unroll
    for (int i = 0; i < 4; i++) {
        int node = base + r0 + i;
        if (node < NN) {
            __half2 l01 = __floats2half2_rn(acc[i][0] + bl[0], acc[i][1] + bl[1]);
            __half2 l23 = __floats2half2_rn(acc[i][2] + bl[2], acc[i][3] + bl[3]);
            __half2 l45 = __floats2half2_rn(acc[i][4] + bl[4], acc[i][5] + bl[5]);
            uint4 ol;
            ol.x = *(uint32_t*)&l01; ol.y = *(uint32_t*)&l23;
            ol.z = *(uint32_t*)&l45; ol.w = 0u;
            g_xlh[node] = ol;
            __half2 r01 = __floats2half2_rn(acc[i][6] + br[0], acc[i][7] + br[1]);
            __half2 r23 = __floats2half2_rn(acc[i][8] + br[2], acc[i][9] + br[3]);
            __half2 r45 = __floats2half2_rn(acc[i][10] + br[4], acc[i][11] + br[5]);
            uint4 orr;
            orr.x = *(uint32_t*)&r01; orr.y = *(uint32_t*)&r23;
            orr.z = *(uint32_t*)&r45; orr.w = 0u;
            g_xrh[node] = orr;
        }
    }
}

// -------- fused edge pass: two-phase (batched gathers, then compute+RED) --------
__device__ __forceinline__ void edge_compute_red(int d, uint4 ua, uint4 ub,
                                                 __half2 at01, __half2 at23,
                                                 __half2 at45, __half2 c02) {
    __half2 xl01 = *(__half2*)&ua.x;
    __half2 xl23 = *(__half2*)&ua.y;
    __half2 xl45 = *(__half2*)&ua.z;
    __half2 e01 = __hadd2(xl01, *(__half2*)&ub.x);
    __half2 e23 = __hadd2(xl23, *(__half2*)&ub.y);
    __half2 e45 = __hadd2(xl45, *(__half2*)&ub.z);
    e01 = __hmax2(e01, __hmul2(e01, c02));
    e23 = __hmax2(e23, __hmul2(e23, c02));
    e45 = __hmax2(e45, __hmul2(e45, c02));
    __half2 sc = __hmul2(at01, e01);
    sc = __hfma2(at23, e23, sc);
    sc = __hfma2(at45, e45, sc);
    float p = ex2f(__low2float(sc) + __high2float(sc));
    __half2 ph = __float2half2_rn(p);
    __half2 n01 = __hmul2(ph, xl01);
    __half2 n23 = __hmul2(ph, xl23);
    __half2 n45 = __hmul2(ph, xl45);
    __half2 n67 = __halves2half2(__low2half(ph), __ushort_as_half(0));
    red_add_v4h(&g_aggh[d], *(uint32_t*)&n01, *(uint32_t*)&n23,
                *(uint32_t*)&n45, *(uint32_t*)&n67);
}

__global__ void k_edge8(const int* __restrict__ ei, const float* __restrict__ att) {
    int t = blockIdx.x * 128 + threadIdx.x;
    const int OE = EE / 8;          // 800,000
    const int ON = NN / 8;          // 25,000
    const float L2E = 1.44269504f;
    __half2 at01 = __floats2half2_rn(__ldg(&att[0]) * L2E, __ldg(&att[1]) * L2E);
    __half2 at23 = __floats2half2_rn(__ldg(&att[2]) * L2E, __ldg(&att[3]) * L2E);
    __half2 at45 = __floats2half2_rn(__ldg(&att[4]) * L2E, __ldg(&att[5]) * L2E);
    __half2 c02 = __floats2half2_rn(0.2f, 0.2f);
    if (t < OE) {
        int4 s0 = __ldg((const int4*)&ei[t * 8]);
        int4 s1 = __ldg((const int4*)&ei[t * 8 + 4]);
        int4 d0 = __ldg((const int4*)&ei[EE + t * 8]);
        int4 d1 = __ldg((const int4*)&ei[EE + t * 8 + 4]);
        int ss[8] = {s0.x, s0.y, s0.z, s0.w, s1.x, s1.y, s1.z, s1.w};
        int dd[8] = {d0.x, d0.y, d0.z, d0.w, d1.x, d1.y, d1.z, d1.w};
        uint4 ua[8], ub[8];
        // phase 1: batch all 16 gathers (no fences between -> MLP_eff ~16)
#pragma unroll
        for (int j = 0; j < 8; j++) ua[j] = __ldg(&g_xlh[ss[j]]);
#pragma unroll
        for (int j = 0; j < 8; j++) ub[j] = __ldg(&g_xrh[dd[j]]);
        // phase 2: compute + RED (register-only math; REDs fence no loads)
#pragma unroll
        for (int j = 0; j < 8; j++)
            edge_compute_red(dd[j], ua[j], ub[j], at01, at23, at45, c02);
    } else if (t < OE + ON) {
        int base = (t - OE) * 8;
        uint4 ua[8], ub[8];
#pragma unroll
        for (int j = 0; j < 8; j++) ua[j] = __ldg(&g_xlh[base + j]);
#pragma unroll
        for (int j = 0; j < 8; j++) ub[j] = __ldg(&g_xrh[base + j]);
#pragma unroll
        for (int j = 0; j < 8; j++)
            edge_compute_red(base + j, ua[j], ub[j], at01, at23, at45, c02);
    }
}

// -------- node: warp-aggregated pooled sums (sorted batch) --------
__global__ void k_node(const int* __restrict__ batch, const float* __restrict__ convb,
                       const float* __restrict__ jkW, const float* __restrict__ jkb) {
    int n = blockIdx.x * 256 + threadIdx.x;
    int lane = threadIdx.x & 31;
    float h0 = 0.f, h1 = 0.f, h2 = 0.f, h3 = 0.f, cnt = 0.f;
    int b = -1;
    if (n < NN) {
        uint4 av = g_aggh[n];
        float2 s01 = __half22float2(*(__half2*)&av.x);
        float2 s23 = __half22float2(*(__half2*)&av.y);
        float2 s45 = __half22float2(*(__half2*)&av.z);
        float2 s67 = __half22float2(*(__half2*)&av.w);
        float inv = 1.f / s67.x;
        float x1[6];
        x1[0] = lrelu(s01.x * inv + convb[0], 0.01f);
        x1[1] = lrelu(s01.y * inv + convb[1], 0.01f);
        x1[2] = lrelu(s23.x * inv + convb[2], 0.01f);
        x1[3] = lrelu(s23.y * inv + convb[3], 0.01f);
        x1[4] = lrelu(s45.x * inv + convb[4], 0.01f);
        x1[5] = lrelu(s45.y * inv + convb[5], 0.01f);
        h0 = jkb[0]; h1 = jkb[1]; h2 = jkb[2]; h3 = jkb[3];
#pragma unroll
        for (int k = 0; k < 6; k++) {
            h0 += x1[k] * jkW[k * 4 + 0];
            h1 += x1[k] * jkW[k * 4 + 1];
            h2 += x1[k] * jkW[k * 4 + 2];
            h3 += x1[k] * jkW[k * 4 + 3];
        }
        cnt = 1.f;
        b = batch[n];
    }
    int b0 = __shfl_sync(0xffffffffu, b, 0);
    bool uni = __all_sync(0xffffffffu, b == b0);
    if (uni) {
        if (b0 >= 0) {
#pragma unroll
            for (int o = 16; o; o >>= 1) {
                h0 += __shfl_xor_sync(0xffffffffu, h0, o);
                h1 += __shfl_xor_sync(0xffffffffu, h1, o);
                h2 += __shfl_xor_sync(0xffffffffu, h2, o);
                h3 += __shfl_xor_sync(0xffffffffu, h3, o);
                cnt += __shfl_xor_sync(0xffffffffu, cnt, o);
            }
            if (lane == 0) {
                atomicAdd(&g_pooled[b0 * 8 + 0], h0);
                atomicAdd(&g_pooled[b0 * 8 + 1], h1);
                atomicAdd(&g_pooled[b0 * 8 + 2], h2);
                atomicAdd(&g_pooled[b0 * 8 + 3], h3);
                atomicAdd(&g_pooled[b0 * 8 + 4], cnt);
            }
        }
    } else if (b >= 0) {
        atomicAdd(&g_pooled[b * 8 + 0], h0);
        atomicAdd(&g_pooled[b * 8 + 1], h1);
        atomicAdd(&g_pooled[b * 8 + 2], h2);
        atomicAdd(&g_pooled[b * 8 + 3], h3);
        atomicAdd(&g_pooled[b * 8 + 4], cnt);
    }
}

// -------- GEMM1 via mma.sync bf16 hi/lo split + double-buffered SMEM (scalar LDS) ----
#define GSTR 72
#define GS_AH 0
#define GS_AL 18432
#define GS_BH 36864
#define GS_BL 55296
#define GS_BUF 73728
#define GS_TOTAL (2 * GS_BUF)

__global__ void __launch_bounds__(256, 1) k_gemm1_mma(const float* __restrict__ A,
                                                      const float* __restrict__ Bw,
                                                      const float* __restrict__ bias) {
    extern __shared__ char sm[];
    int tid = threadIdx.x;
    int lane = tid & 31, wid = tid >> 5;
    int bm = blockIdx.y * 128, bn = blockIdx.x * 128;
    int wm = (wid & 1) * 64, wn = (wid >> 1) * 32;

    float acc[4][4][4];
#pragma unroll
    for (int mt = 0; mt < 4; mt++)
#pragma unroll
        for (int nt = 0; nt < 4; nt++)
#pragma unroll
            for (int q = 0; q < 4; q++) acc[mt][nt][q] = 0.f;

    float4 pa[8];
    float pb[8][4];

    // prefetch tile 0 into registers
    {
        const float* Ab = A + (size_t)bm * KK;
#pragma unroll
        for (int i = 0; i < 8; i++) {
            int fid = i * 256 + tid;
            int row = fid >> 4;
            int c4 = (fid & 15) * 4;
            pa[i] = *(const float4*)&Ab[(size_t)row * KK + c4];
        }
        const float* Bb = Bw + bn;
#pragma unroll
        for (int i = 0; i < 8; i++) {
            int fid = i * 256 + tid;
            int n = fid & 127;
            int kq = (fid >> 7) * 4;
#pragma unroll
            for (int j = 0; j < 4; j++) pb[i][j] = Bb[(size_t)(kq + j) * 256 + n];
        }
    }
    // store tile 0 -> buf0
    {
        char* buf = sm;
#pragma unroll
        for (int i = 0; i < 8; i++) {
            int fid = i * 256 + tid;
            int row = fid >> 4;
            int c4 = (fid & 15) * 4;
            float4 v = pa[i];
            float hx = __bfloat162float(__float2bfloat16(v.x));
            float hy = __bfloat162float(__float2bfloat16(v.y));
            float hz = __bfloat162float(__float2bfloat16(v.z));
            float hw = __bfloat162float(__float2bfloat16(v.w));
            uint32_t off = (uint32_t)(row * GSTR + c4) * 2;
            *(uint2*)(buf + GS_AH + off) = make_uint2(pack_bf16x2(hx, hy), pack_bf16x2(hz, hw));
            *(uint2*)(buf + GS_AL + off) =
                make_uint2(pack_bf16x2(v.x - hx, v.y - hy), pack_bf16x2(v.z - hz, v.w - hw));
        }
#pragma unroll
        for (int i = 0; i < 8; i++) {
            int fid = i * 256 + tid;
            int n = fid & 127;
            int kq = (fid >> 7) * 4;
            float b0 = pb[i][0], b1 = pb[i][1], b2 = pb[i][2], b3 = pb[i][3];
            float h0 = __bfloat162float(__float2bfloat16(b0));
            float h1 = __bfloat162float(__float2bfloat16(b1));
            float h2 = __bfloat162float(__float2bfloat16(b2));
            float h3 = __bfloat162float(__float2bfloat16(b3));
            uint32_t off = (uint32_t)(n * GSTR + kq) * 2;
            *(uint2*)(buf + GS_BH + off) = make_uint2(pack_bf16x2(h0, h1), pack_bf16x2(h2, h3));
            *(uint2*)(buf + GS_BL + off) =
                make_uint2(pack_bf16x2(b0 - h0, b1 - h1), pack_bf16x2(b2 - h2, b3 - h3));
        }
    }
    __syncthreads();

    for (int kt = 0; kt < 40; kt++) {
        char* cur = sm + (size_t)(kt & 1) * GS_BUF;
        char* nxt = sm + (size_t)((kt + 1) & 1) * GS_BUF;

        // prefetch next tile into registers (hidden behind MMA)
        if (kt < 39) {
            const float* Ab = A + (size_t)bm * KK + (kt + 1) * 64;
#pragma unroll
            for (int i = 0; i < 8; i++) {
                int fid = i * 256 + tid;
                int row = fid >> 4;
                int c4 = (fid & 15) * 4;
                pa[i] = *(const float4*)&Ab[(size_t)row * KK + c4];
            }
            const float* Bb = Bw + (size_t)((kt + 1) * 64) * 256 + bn;
#pragma unroll
            for (int i = 0; i < 8; i++) {
                int fid = i * 256 + tid;
                int n = fid & 127;
                int kq = (fid >> 7) * 4;
#pragma unroll
                for (int j = 0; j < 4; j++) pb[i][j] = Bb[(size_t)(kq + j) * 256 + n];
            }
        }

        // ---- compute from cur ----
#pragma unroll
        for (int kk = 0; kk < 4; kk++) {
            int kc = kk * 16 + (lane & 3) * 2;
            uint32_t ah[4][4], al[4][4];
#pragma unroll
            for (int mt = 0; mt < 4; mt++) {
                int r = wm + mt * 16 + (lane >> 2);
                uint32_t o00 = (uint32_t)(r * GSTR + kc) * 2;
                uint32_t o10 = (uint32_t)((r + 8) * GSTR + kc) * 2;
                ah[mt][0] = *(const uint32_t*)(cur + GS_AH + o00);
                ah[mt][1] = *(const uint32_t*)(cur + GS_AH + o10);
                ah[mt][2] = *(const uint32_t*)(cur + GS_AH + o00 + 16);
                ah[mt][3] = *(const uint32_t*)(cur + GS_AH + o10 + 16);
                al[mt][0] = *(const uint32_t*)(cur + GS_AL + o00);
                al[mt][1] = *(const uint32_t*)(cur + GS_AL + o10);
                al[mt][2] = *(const uint32_t*)(cur + GS_AL + o00 + 16);
                al[mt][3] = *(const uint32_t*)(cur + GS_AL + o10 + 16);
            }
            uint32_t bh[4][2], bl[4][2];
#pragma unroll
            for (int nt = 0; nt < 4; nt++) {
                int n = wn + nt * 8 + (lane >> 2);
                uint32_t o = (uint32_t)(n * GSTR + kc) * 2;
                bh[nt][0] = *(const uint32_t*)(cur + GS_BH + o);
                bh[nt][1] = *(const uint32_t*)(cur + GS_BH + o + 16);
                bl[nt][0] = *(const uint32_t*)(cur + GS_BL + o);
                bl[nt][1] = *(const uint32_t*)(cur + GS_BL + o + 16);
            }
#pragma unroll
            for (int mt = 0; mt < 4; mt++)
#pragma unroll
                for (int nt = 0; nt < 4; nt++) {
                    mma_bf16(acc[mt][nt], ah[mt], bh[nt]);
                    mma_bf16(acc[mt][nt], ah[mt], bl[nt]);
                    mma_bf16(acc[mt][nt], al[mt], bh[nt]);
                }
        }

        // ---- store next tile (regs ready; LDG latency hidden by MMAs) ----
        if (kt < 39) {
#pragma unroll
            for (int i = 0; i < 8; i++) {
                int fid = i * 256 + tid;
                int row = fid >> 4;
                int c4 = (fid & 15) * 4;
                float4 v = pa[i];
                float hx = __bfloat162float(__float2bfloat16(v.x));
                float hy = __bfloat162float(__float2bfloat16(v.y));
                float hz = __bfloat162float(__float2bfloat16(v.z));
                float hw = __bfloat162float(__float2bfloat16(v.w));
                uint32_t off = (uint32_t)(row * GSTR + c4) * 2;
                *(uint2*)(nxt + GS_AH + off) =
                    make_uint2(pack_bf16x2(hx, hy), pack_bf16x2(hz, hw));
                *(uint2*)(nxt + GS_AL + off) =
                    make_uint2(pack_bf16x2(v.x - hx, v.y - hy), pack_bf16x2(v.z - hz, v.w - hw));
            }
#pragma unroll
            for (int i = 0; i < 8; i++) {
                int fid = i * 256 + tid;
                int n = fid & 127;
                int kq = (fid >> 7) * 4;
                float b0 = pb[i][0], b1 = pb[i][1], b2 = pb[i][2], b3 = pb[i][3];
                float h0 = __bfloat162float(__float2bfloat16(b0));
                float h1 = __bfloat162float(__float2bfloat16(b1));
                float h2 = __bfloat162float(__float2bfloat16(b2));
                float h3 = __bfloat162float(__float2bfloat16(b3));
                uint32_t off = (uint32_t)(n * GSTR + kq) * 2;
                *(uint2*)(nxt + GS_BH + off) =
                    make_uint2(pack_bf16x2(h0, h1), pack_bf16x2(h2, h3));
                *(uint2*)(nxt + GS_BL + off) =
                    make_uint2(pack_bf16x2(b0 - h0, b1 - h1), pack_bf16x2(b2 - h2, b3 - h3));
            }
            __syncthreads();
        }
    }
#pragma unroll
    for (int mt = 0; mt < 4; mt++) {
        int r = bm + wm + mt * 16 + (lane >> 2);
#pragma unroll
        for (int nt = 0; nt < 4; nt++) {
            int c = bn + wn + nt * 8 + (lane & 3) * 2;
            float bx = bias[c], by = bias[c + 1];
            *(float2*)&g_f1[(size_t)r * 256 + c] =
                make_float2(acc[mt][nt][0] + bx, acc[mt][nt][1] + by);
            *(float2*)&g_f1[(size_t)(r + 8) * 256 + c] =
                make_float2(acc[mt][nt][2] + bx, acc[mt][nt][3] + by);
        }
    }
}

// -------- fused LN1+leaky + GEMM2 + LN2+leaky  (16 rows/block, 256 thr, 4 out/thr) ----
__global__ void __launch_bounds__(256) k_l2f(const float* __restrict__ g1,
                                             const float* __restrict__ b1,
                                             const float* __restrict__ W,
                                             const float* __restrict__ b2,
                                             const float* __restrict__ gg,
                                             const float* __restrict__ bb) {
    __shared__ float xs[16][264];
    int tid = threadIdx.x;
    int r = tid >> 4;      // 0..15
    int cg = tid & 15;     // 0..15
    size_t row = (size_t)(blockIdx.x * 16 + r);
    const float4* f1v = (const float4*)&g_f1[row * 256];
    float4 v[4];
    float s = 0.f, q = 0.f;
#pragma unroll
    for (int i = 0; i < 4; i++) {
        v[i] = f1v[cg * 4 + i];
        s += v[i].x + v[i].y + v[i].z + v[i].w;
        q += v[i].x * v[i].x + v[i].y * v[i].y + v[i].z * v[i].z + v[i].w * v[i].w;
    }
#pragma unroll
    for (int o = 8; o; o >>= 1) {
        s += __shfl_xor_sync(0xffffffffu, s, o);
        q += __shfl_xor_sync(0xffffffffu, q, o);
    }
    float mu = s * (1.f / 256.f);
    float var = q * (1.f / 256.f) - mu * mu;
    float rs = rsqrtf(var + 1e-5f);
#pragma unroll
    for (int i = 0; i < 4; i++) {
        int c0 = cg * 16 + i * 4;
        float4 gv = *(const float4*)&g1[c0];
        float4 bv = *(const float4*)&b1[c0];
        xs[r][c0 + 0] = lrelu((v[i].x - mu) * rs * gv.x + bv.x, 0.01f);
        xs[r][c0 + 1] = lrelu((v[i].y - mu) * rs * gv.y + bv.y, 0.01f);
        xs[r][c0 + 2] = lrelu((v[i].z - mu) * rs * gv.z + bv.z, 0.01f);
        xs[r][c0 + 3] = lrelu((v[i].w - mu) * rs * gv.w + bv.w, 0.01f);
    }
    __syncthreads();
    int c = cg * 4;
    float4 acc = *(const float4*)&b2[c];
    const float4* W4 = (const float4*)W;
#pragma unroll 8
    for (int k = 0; k < 256; k++) {
        float xv = xs[r][k];
        float4 w = W4[k * 16 + cg];
        acc.x += xv * w.x; acc.y += xv * w.y; acc.z += xv * w.z; acc.w += xv * w.w;
    }
    float s2 = acc.x + acc.y + acc.z + acc.w;
    float q2 = acc.x * acc.x + acc.y * acc.y + acc.z * acc.z + acc.w * acc.w;
#pragma unroll
    for (int o = 8; o; o >>= 1) {
        s2 += __shfl_xor_sync(0xffffffffu, s2, o);
        q2 += __shfl_xor_sync(0xffffffffu, q2, o);
    }
    float mu2 = s2 * (1.f / 64.f);
    float var2 = q2 * (1.f / 64.f) - mu2 * mu2;
    float rs2 = rsqrtf(var2 + 1e-5f);
    float4 gv = *(const float4*)&gg[c];
    float4 bv = *(const float4*)&bb[c];
    float4 o4;
    o4.x = lrelu((acc.x - mu2) * rs2 * gv.x + bv.x, 0.01f);
    o4.y = lrelu((acc.y - mu2) * rs2 * gv.y + bv.y, 0.01f);
    o4.z = lrelu((acc.z - mu2) * rs2 * gv.z + bv.z, 0.01f);
    o4.w = lrelu((acc.w - mu2) * rs2 * gv.w + bv.w, 0.01f);
    *(float4*)&g_f2[row * 64 + c] = o4;
}

// -------- GEMM3 [*,64]->[*,8] fused with LN3 + leaky --------
__global__ void k_l3(const float* __restrict__ W, const float* __restrict__ b3,
                     const float* __restrict__ gg, const float* __restrict__ bb) {
    __shared__ float xs[32][65];
    __shared__ float w3[512];
    int tid = threadIdx.x;
#pragma unroll
    for (int i = 0; i < 2; i++) w3[i * 256 + tid] = W[i * 256 + tid];
#pragma unroll
    for (int i = 0; i < 2; i++) {
        int fid = i * 256 + tid;
        int rr = fid / 16, cc = (fid % 16) * 4;
        float4 v = *(const float4*)&g_f2[(blockIdx.x * 32 + rr) * 64 + cc];
        xs[rr][cc + 0] = v.x; xs[rr][cc + 1] = v.y; xs[rr][cc + 2] = v.z; xs[rr][cc + 3] = v.w;
    }
    __syncthreads();
    int r = tid / 8, c = tid % 8;
    float acc = b3[c];
#pragma unroll 8
    for (int k = 0; k < 64; k++) acc += xs[r][k] * w3[k * 8 + c];
    float s = acc, q = acc * acc;
#pragma unroll
    for (int o = 4; o; o >>= 1) {
        s += __shfl_xor_sync(0xffffffffu, s, o);
        q += __shfl_xor_sync(0xffffffffu, q, o);
    }
    float mu = s * (1.f / 8.f);
    float var = q * (1.f / 8.f) - mu * mu;
    float y = (acc - mu) * rsqrtf(var + 1e-5f) * gg[c] + bb[c];
    g_f3[(blockIdx.x * 32 + r) * 8 + c] = lrelu(y, 0.01f);
}

// -------- flatten: [B,1024]@[1024,32] + LN4 + leaky  (512 threads) --------
__global__ void k_flat(const float* __restrict__ W, const float* __restrict__ fb,
                       const float* __restrict__ gg, const float* __restrict__ bb) {
    __shared__ float xs[1024];
    __shared__ float part[512];
    int b = blockIdx.x, tid = threadIdx.x;   // 512 threads
    if (tid < 256) {
        *(float4*)&xs[tid * 4] = *(const float4*)&g_f3[b * 1024 + tid * 4];
    }
    __syncthreads();
    int c = tid & 31, qr = tid >> 5;        // 16 chunks of 64 k
    float acc = 0.f;
#pragma unroll 8
    for (int k = qr * 64; k < qr * 64 + 64; k++) acc += xs[k] * W[k * 32 + c];
    part[tid] = acc;
    __syncthreads();
    if (tid < 32) {
        float a = fb[tid];
#pragma unroll
        for (int j = 0; j < 16; j++) a += part[tid + 32 * j];
        float s = a, q = a * a;
#pragma unroll
        for (int o = 16; o; o >>= 1) {
            s += __shfl_xor_sync(0xffffffffu, s, o);
            q += __shfl_xor_sync(0xffffffffu, q, o);
        }
        float mu = s * (1.f / 32.f);
        float var = q * (1.f / 32.f) - mu * mu;
        g_xf[b * 32 + tid] = lrelu((a - mu) * rsqrtf(var + 1e-5f) * gg[tid] + bb[tid], 0.01f);
    }
}

// -------- final --------
__global__ void k_final(const float* __restrict__ oneh, const float* __restrict__ W,
                        const float* __restrict__ ob, float* __restrict__ out) {
    int tid = threadIdx.x;
    if (tid >= 128) return;
    int b = tid >> 1, o = tid & 1;
    float acc = ob[o];
    float cnt = fmaxf(g_pooled[b * 8 + 4], 1.f);
    float ic = 1.f / cnt;
#pragma unroll
    for (int j = 0; j < 4; j++) acc += g_pooled[b * 8 + j] * ic * W[j * 2 + o];
#pragma unroll
    for (int j = 0; j < 32; j++) acc += g_xf[b * 32 + j] * W[(4 + j) * 2 + o];
#pragma unroll
    for (int j = 0; j < 20; j++) acc += oneh[b * 20 + j] * W[(36 + j) * 2 + o];
    out[b * 2 + o] = acc;
}

extern "C" void kernel_launch(void* const* d_in, const int* in_sizes, int n_in,
                              void* d_out, int out_size) {
    const float *x, *features, *one_hot, *W_l, *b_l, *W_r, *b_r, *att, *conv_b, *jk_W, *jk_b;
    const float *l1_W, *l1_b, *ln1_g, *ln1_b, *l2_W, *l2_b, *ln2_g, *ln2_b;
    const float *l3_W, *l3_b, *ln3_g, *ln3_b, *fl_W, *fl_b, *ln4_g, *ln4_b, *out_W, *out_b;
    const int *edge_index, *batch;

    if (in_sizes[1] == 2 * EE) {
        x = (const float*)d_in[0]; edge_index = (const int*)d_in[1]; batch = (const int*)d_in[2];
        features = (const float*)d_in[3]; one_hot = (const float*)d_in[4];
        W_l = (const float*)d_in[5]; b_l = (const float*)d_in[6];
        W_r = (const float*)d_in[7]; b_r = (const float*)d_in[8];
        att = (const float*)d_in[9]; conv_b = (const float*)d_in[10];
        jk_W = (const float*)d_in[11]; jk_b = (const float*)d_in[12];
        l1_W = (const float*)d_in[13]; l1_b = (const float*)d_in[14];
        ln1_g = (const float*)d_in[15]; ln1_b = (const float*)d_in[16];
        l2_W = (const float*)d_in[17]; l2_b = (const float*)d_in[18];
        ln2_g = (const float*)d_in[19]; ln2_b = (const float*)d_in[20];
        l3_W = (const float*)d_in[21]; l3_b = (const float*)d_in[22];
        ln3_g = (const float*)d_in[23]; ln3_b = (const float*)d_in[24];
        fl_W = (const float*)d_in[25]; fl_b = (const float*)d_in[26];
        ln4_g = (const float*)d_in[27]; ln4_b = (const float*)d_in[28];
        out_W = (const float*)d_in[29]; out_b = (const float*)d_in[30];
    } else {
        x = (const float*)d_in[0]; features = (const float*)d_in[1]; one_hot = (const float*)d_in[2];
        W_l = (const float*)d_in[3]; b_l = (const float*)d_in[4];
        W_r = (const float*)d_in[5]; b_r = (const float*)d_in[6];
        att = (const float*)d_in[7]; conv_b = (const float*)d_in[8];
        jk_W = (const float*)d_in[9]; jk_b = (const float*)d_in[10];
        l1_W = (const float*)d_in[11]; l1_b = (const float*)d_in[12];
        ln1_g = (const float*)d_in[13]; ln1_b = (const float*)d_in[14];
        l2_W = (const float*)d_in[15]; l2_b = (const float*)d_in[16];
        ln2_g = (const float*)d_in[17]; ln2_b = (const float*)d_in[18];
        l3_W = (const float*)d_in[19]; l3_b = (const float*)d_in[20];
        ln3_g = (const float*)d_in[21]; ln3_b = (const float*)d_in[22];
        fl_W = (const float*)d_in[23]; fl_b = (const float*)d_in[24];
        ln4_g = (const float*)d_in[25]; ln4_b = (const float*)d_in[26];
        out_W = (const float*)d_in[27]; out_b = (const float*)d_in[28];
        edge_index = (const int*)d_in[29]; batch = (const int*)d_in[30];
    }

    static cudaStream_t s1 = nullptr, s2 = nullptr, s3 = nullptr;
    static cudaEvent_t evF = nullptr, evJ = nullptr, evZ = nullptr, evG = nullptr;
    if (s1 == nullptr) {
        int loPri, hiPri;
        cudaDeviceGetStreamPriorityRange(&loPri, &hiPri);
        cudaStreamCreateWithPriority(&s1, cudaStreamNonBlocking, hiPri);   // GNN (critical)
        cudaStreamCreateWithPriority(&s2, cudaStreamNonBlocking, loPri);   // MLP (slack)
        cudaStreamCreateWithPriority(&s3, cudaStreamNonBlocking, hiPri);   // zero (critical)
        cudaEventCreateWithFlags(&evF, cudaEventDisableTiming);
        cudaEventCreateWithFlags(&evJ, cudaEventDisableTiming);
        cudaEventCreateWithFlags(&evZ, cudaEventDisableTiming);
        cudaEventCreateWithFlags(&evG, cudaEventDisableTiming);
        cudaFuncSetAttribute(k_gemm1_mma, cudaFuncAttributeMaxDynamicSharedMemorySize, GS_TOTAL);
    }

    // fork from legacy stream
    cudaEventRecord(evF, 0);
    cudaStreamWaitEvent(s1, evF, 0);
    cudaStreamWaitEvent(s2, evF, 0);
    cudaStreamWaitEvent(s3, evF, 0);

    // MLP chain (low priority — has slack under the GNN chain)
    k_gemm1_mma<<<dim3(2, 64), 256, GS_TOTAL, s2>>>(features, l1_W, l1_b);
    k_l2f<<<MM / 16, 256, 0, s2>>>(ln1_g, ln1_b, l2_W, l2_b, ln2_g, ln2_b);
    k_l3<<<MM / 32, 256, 0, s2>>>(l3_W, l3_b, ln3_g, ln3_b);
    k_flat<<<BB, 512, 0, s2>>>(fl_W, fl_b, ln4_g, ln4_b);
    cudaEventRecord(evJ, s2);

    // zeroing (high priority, parallel with xlxr)
    k_zero<<<(NN + 255) / 256, 256, 0, s3>>>();
    cudaEventRecord(evZ, s3);

    // GNN chain (high priority — critical path)
    k_xlxr<<<(NN + 511) / 512, 128, 0, s1>>>(x, W_l, W_r, b_l, b_r);
    cudaStreamWaitEvent(s1, evZ, 0);
    k_edge8<<<(EE / 8 + NN / 8 + 127) / 128, 128, 0, s1>>>(edge_index, att);
    k_node<<<(NN + 255) / 256, 256, 0, s1>>>(batch, conv_b, jk_W, jk_b);
    cudaEventRecord(evG, s1);

    // join on legacy stream
    cudaStreamWaitEvent(0, evG, 0);
    cudaStreamWaitEvent(0, evJ, 0);
    k_final<<<1, 128>>>(one_hot, out_W, out_b, (float*)d_out);
}

// round 16
// speedup vs baseline: 1.1157x; 1.1157x over previous
#include <cuda_runtime.h>
#include <cuda_bf16.h>
#include <cuda_fp16.h>
#include <cstdint>

#define NN 200000
#define EE 6400000
#define BB 64
#define MM 8192
#define KK 2560

// -------- scratch (device globals; no allocation allowed) --------
__device__ uint4 g_xlh[NN];          // 6 fp16 + pad per node
__device__ uint4 g_xrh[NN];
__device__ uint4 g_aggh[NN];         // 8 fp16: [0..5]=sum p*xl, [6]=sum p, [7]=pad
__device__ float g_pooled[BB * 8];   // [0..3]=sum h, [4]=count
__device__ float g_f1[MM * 256];
__device__ float g_f2[MM * 64];
__device__ float g_f3[MM * 8];
__device__ float g_xf[BB * 32];

__device__ __forceinline__ float lrelu(float v, float s) { return v >= 0.f ? v : s * v; }

__device__ __forceinline__ void red_add_v4h(uint4* addr, uint32_t a, uint32_t b,
                                            uint32_t c, uint32_t d) {
    asm volatile("red.relaxed.gpu.global.add.noftz.v4.f16x2 [%0], {%1,%2,%3,%4};"
                 :: "l"(addr), "r"(a), "r"(b), "r"(c), "r"(d) : "memory");
}

__device__ __forceinline__ float ex2f(float x) {
    float r;
    asm("ex2.approx.f32 %0, %1;" : "=f"(r) : "f"(x));
    return r;
}

__device__ __forceinline__ uint32_t pack_bf16x2(float lo, float hi) {
    uint32_t r;
    asm("cvt.rn.bf16x2.f32 %0, %1, %2;" : "=r"(r) : "f"(hi), "f"(lo));
    return r;
}

__device__ __forceinline__ void mma_bf16(float (&c)[4], const uint32_t (&a)[4],
                                         const uint32_t (&b)[2]) {
    asm volatile(
        "mma.sync.aligned.m16n8k16.row.col.f32.bf16.bf16.f32 "
        "{%0,%1,%2,%3}, {%4,%5,%6,%7}, {%8,%9}, {%0,%1,%2,%3};"
        : "+f"(c[0]), "+f"(c[1]), "+f"(c[2]), "+f"(c[3])
        : "r"(a[0]), "r"(a[1]), "r"(a[2]), "r"(a[3]), "r"(b[0]), "r"(b[1]));
}

// -------- zero pooled only (g_aggh initialized by k_xlxr self-loop fold) --------
__global__ void k_zero() {
    int i = threadIdx.x;
    if (i < BB * 2) *(float4*)&g_pooled[i * 4] = make_float4(0.f, 0.f, 0.f, 0.f);
}

// -------- xl/xr transform + self-loop fold: g_aggh[n] = (p_self*xl, p_self, 0) --------
__global__ void k_xlxr(const float* __restrict__ x, const float* __restrict__ Wl,
                       const float* __restrict__ Wr, const float* __restrict__ bl,
                       const float* __restrict__ br, const float* __restrict__ att) {
    __shared__ float xs[16][516];
    __shared__ float sW[128][12];
    int tid = threadIdx.x;          // 128 threads
    const float L2E = 1.44269504f;
    float at[6];
#pragma unroll
    for (int j = 0; j < 6; j++) at[j] = __ldg(&att[j]) * L2E;
    for (int i = tid; i < 768; i += 128) {
        int k = i / 6, j = i % 6;
        sW[k][j]     = Wl[i];
        sW[k][j + 6] = Wr[i];
    }
    int base = blockIdx.x * 512;
    float acc[4][12];
#pragma unroll
    for (int i = 0; i < 4; i++)
#pragma unroll
        for (int j = 0; j < 12; j++) acc[i][j] = 0.f;
    int r0 = tid * 4;
    for (int kt = 0; kt < 8; kt++) {
        int k0 = kt * 16;
        __syncthreads();
#pragma unroll
        for (int it = 0; it < 16; it++) {
            int fid = it * 128 + tid;
            int r = fid >> 2;
            int c4 = (fid & 3) * 4;
            int row = base + r;
            float4 v = make_float4(0.f, 0.f, 0.f, 0.f);
            if (row < NN) v = *(const float4*)&x[row * 128 + k0 + c4];
            xs[c4 + 0][r] = v.x; xs[c4 + 1][r] = v.y;
            xs[c4 + 2][r] = v.z; xs[c4 + 3][r] = v.w;
        }
        __syncthreads();
#pragma unroll
        for (int k = 0; k < 16; k++) {
            float w[12];
#pragma unroll
            for (int j = 0; j < 12; j++) w[j] = sW[k0 + k][j];
            float4 xa = *(const float4*)&xs[k][r0];
            float xv[4] = {xa.x, xa.y, xa.z, xa.w};
#pragma unroll
            for (int i = 0; i < 4; i++)
#pragma unroll
                for (int j = 0; j < 12; j++) acc[i][j] += xv[i] * w[j];
        }
    }
#pragma unroll
    for (int i = 0; i < 4; i++) {
        int node = base + r0 + i;
        if (node < NN) {
            float l0 = acc[i][0] + bl[0], l1 = acc[i][1] + bl[1], l2 = acc[i][2] + bl[2];
            float l3 = acc[i][3] + bl[3], l4 = acc[i][4] + bl[4], l5 = acc[i][5] + bl[5];
            float r0v = acc[i][6] + br[0], r1v = acc[i][7] + br[1], r2v = acc[i][8] + br[2];
            float r3v = acc[i][9] + br[3], r4v = acc[i][10] + br[4], r5v = acc[i][11] + br[5];
            // packed fp16 tables for the edge pass
            __half2 l01 = __floats2half2_rn(l0, l1);
            __half2 l23 = __floats2half2_rn(l2, l3);
            __half2 l45 = __floats2half2_rn(l4, l5);
            uint4 ol;
            ol.x = *(uint32_t*)&l01; ol.y = *(uint32_t*)&l23;
            ol.z = *(uint32_t*)&l45; ol.w = 0u;
            g_xlh[node] = ol;
            __half2 q01 = __floats2half2_rn(r0v, r1v);
            __half2 q23 = __floats2half2_rn(r2v, r3v);
            __half2 q45 = __floats2half2_rn(r4v, r5v);
            uint4 orr;
            orr.x = *(uint32_t*)&q01; orr.y = *(uint32_t*)&q23;
            orr.z = *(uint32_t*)&q45; orr.w = 0u;
            g_xrh[node] = orr;
            // self-loop fold: initial aggregate = (p*xl, p, 0)
            float e0 = lrelu(l0 + r0v, 0.2f);
            float e1 = lrelu(l1 + r1v, 0.2f);
            float e2 = lrelu(l2 + r2v, 0.2f);
            float e3 = lrelu(l3 + r3v, 0.2f);
            float e4 = lrelu(l4 + r4v, 0.2f);
            float e5 = lrelu(l5 + r5v, 0.2f);
            float p = ex2f(at[0]*e0 + at[1]*e1 + at[2]*e2 + at[3]*e3 + at[4]*e4 + at[5]*e5);
            __half2 n01 = __floats2half2_rn(p * l0, p * l1);
            __half2 n23 = __floats2half2_rn(p * l2, p * l3);
            __half2 n45 = __floats2half2_rn(p * l4, p * l5);
            __half2 n67 = __floats2half2_rn(p, 0.f);
            uint4 oa;
            oa.x = *(uint32_t*)&n01; oa.y = *(uint32_t*)&n23;
            oa.z = *(uint32_t*)&n45; oa.w = *(uint32_t*)&n67;
            g_aggh[node] = oa;
        }
    }
}

// -------- fused edge pass: half2 score + half2 numerator, single v4.f16x2 RED --------
__device__ __forceinline__ void edge_one_h(int s, int d, __half2 at01, __half2 at23,
                                           __half2 at45, __half2 c02) {
    uint4 ua = __ldg(&g_xlh[s]);
    uint4 ub = __ldg(&g_xrh[d]);
    __half2 xl01 = *(__half2*)&ua.x;
    __half2 xl23 = *(__half2*)&ua.y;
    __half2 xl45 = *(__half2*)&ua.z;
    __half2 e01 = __hadd2(xl01, *(__half2*)&ub.x);
    __half2 e23 = __hadd2(xl23, *(__half2*)&ub.y);
    __half2 e45 = __hadd2(xl45, *(__half2*)&ub.z);
    e01 = __hmax2(e01, __hmul2(e01, c02));
    e23 = __hmax2(e23, __hmul2(e23, c02));
    e45 = __hmax2(e45, __hmul2(e45, c02));
    __half2 sc = __hmul2(at01, e01);
    sc = __hfma2(at23, e23, sc);
    sc = __hfma2(at45, e45, sc);
    float p = ex2f(__low2float(sc) + __high2float(sc));
    __half2 ph = __float2half2_rn(p);
    __half2 n01 = __hmul2(ph, xl01);
    __half2 n23 = __hmul2(ph, xl23);
    __half2 n45 = __hmul2(ph, xl45);
    __half2 n67 = __halves2half2(__low2half(ph), __ushort_as_half(0));
    red_add_v4h(&g_aggh[d], *(uint32_t*)&n01, *(uint32_t*)&n23,
                *(uint32_t*)&n45, *(uint32_t*)&n67);
}

__global__ void k_edge8(const int* __restrict__ ei, const float* __restrict__ att) {
    int t = blockIdx.x * 128 + threadIdx.x;
    const int OE = EE / 8;          // 800,000 (self-loops folded into k_xlxr)
    if (t >= OE) return;
    const float L2E = 1.44269504f;
    __half2 at01 = __floats2half2_rn(__ldg(&att[0]) * L2E, __ldg(&att[1]) * L2E);
    __half2 at23 = __floats2half2_rn(__ldg(&att[2]) * L2E, __ldg(&att[3]) * L2E);
    __half2 at45 = __floats2half2_rn(__ldg(&att[4]) * L2E, __ldg(&att[5]) * L2E);
    __half2 c02 = __floats2half2_rn(0.2f, 0.2f);
    int4 s0 = __ldg((const int4*)&ei[t * 8]);
    int4 s1 = __ldg((const int4*)&ei[t * 8 + 4]);
    int4 d0 = __ldg((const int4*)&ei[EE + t * 8]);
    int4 d1 = __ldg((const int4*)&ei[EE + t * 8 + 4]);
    edge_one_h(s0.x, d0.x, at01, at23, at45, c02);
    edge_one_h(s0.y, d0.y, at01, at23, at45, c02);
    edge_one_h(s0.z, d0.z, at01, at23, at45, c02);
    edge_one_h(s0.w, d0.w, at01, at23, at45, c02);
    edge_one_h(s1.x, d1.x, at01, at23, at45, c02);
    edge_one_h(s1.y, d1.y, at01, at23, at45, c02);
    edge_one_h(s1.z, d1.z, at01, at23, at45, c02);
    edge_one_h(s1.w, d1.w, at01, at23, at45, c02);
}

// -------- node: warp-aggregated pooled sums (sorted batch) --------
__global__ void k_node(const int* __restrict__ batch, const float* __restrict__ convb,
                       const float* __restrict__ jkW, const float* __restrict__ jkb) {
    int n = blockIdx.x * 256 + threadIdx.x;
    int lane = threadIdx.x & 31;
    float h0 = 0.f, h1 = 0.f, h2 = 0.f, h3 = 0.f, cnt = 0.f;
    int b = -1;
    if (n < NN) {
        uint4 av = g_aggh[n];
        float2 s01 = __half22float2(*(__half2*)&av.x);
        float2 s23 = __half22float2(*(__half2*)&av.y);
        float2 s45 = __half22float2(*(__half2*)&av.z);
        float2 s67 = __half22float2(*(__half2*)&av.w);
        float inv = 1.f / s67.x;
        float x1[6];
        x1[0] = lrelu(s01.x * inv + convb[0], 0.01f);
        x1[1] = lrelu(s01.y * inv + convb[1], 0.01f);
        x1[2] = lrelu(s23.x * inv + convb[2], 0.01f);
        x1[3] = lrelu(s23.y * inv + convb[3], 0.01f);
        x1[4] = lrelu(s45.x * inv + convb[4], 0.01f);
        x1[5] = lrelu(s45.y * inv + convb[5], 0.01f);
        h0 = jkb[0]; h1 = jkb[1]; h2 = jkb[2]; h3 = jkb[3];
#pragma unroll
        for (int k = 0; k < 6; k++) {
            h0 += x1[k] * jkW[k * 4 + 0];
            h1 += x1[k] * jkW[k * 4 + 1];
            h2 += x1[k] * jkW[k * 4 + 2];
            h3 += x1[k] * jkW[k * 4 + 3];
        }
        cnt = 1.f;
        b = batch[n];
    }
    int b0 = __shfl_sync(0xffffffffu, b, 0);
    bool uni = __all_sync(0xffffffffu, b == b0);
    if (uni) {
        if (b0 >= 0) {
#pragma unroll
            for (int o = 16; o; o >>= 1) {
                h0 += __shfl_xor_sync(0xffffffffu, h0, o);
                h1 += __shfl_xor_sync(0xffffffffu, h1, o);
                h2 += __shfl_xor_sync(0xffffffffu, h2, o);
                h3 += __shfl_xor_sync(0xffffffffu, h3, o);
                cnt += __shfl_xor_sync(0xffffffffu, cnt, o);
            }
            if (lane == 0) {
                atomicAdd(&g_pooled[b0 * 8 + 0], h0);
                atomicAdd(&g_pooled[b0 * 8 + 1], h1);
                atomicAdd(&g_pooled[b0 * 8 + 2], h2);
                atomicAdd(&g_pooled[b0 * 8 + 3], h3);
                atomicAdd(&g_pooled[b0 * 8 + 4], cnt);
            }
        }
    } else if (b >= 0) {
        atomicAdd(&g_pooled[b * 8 + 0], h0);
        atomicAdd(&g_pooled[b * 8 + 1], h1);
        atomicAdd(&g_pooled[b * 8 + 2], h2);
        atomicAdd(&g_pooled[b * 8 + 3], h3);
        atomicAdd(&g_pooled[b * 8 + 4], cnt);
    }
}

// -------- GEMM1 via mma.sync bf16 hi/lo split + double-buffered SMEM (scalar LDS) ----
#define GSTR 72
#define GS_AH 0
#define GS_AL 18432
#define GS_BH 36864
#define GS_BL 55296
#define GS_BUF 73728
#define GS_TOTAL (2 * GS_BUF)

__global__ void __launch_bounds__(256, 1) k_gemm1_mma(const float* __restrict__ A,
                                                      const float* __restrict__ Bw,
                                                      const float* __restrict__ bias) {
    extern __shared__ char sm[];
    int tid = threadIdx.x;
    int lane = tid & 31, wid = tid >> 5;
    int bm = blockIdx.y * 128, bn = blockIdx.x * 128;
    int wm = (wid & 1) * 64, wn = (wid >> 1) * 32;

    float acc[4][4][4];
#pragma unroll
    for (int mt = 0; mt < 4; mt++)
#pragma unroll
        for (int nt = 0; nt < 4; nt++)
#pragma unroll
            for (int q = 0; q < 4; q++) acc[mt][nt][q] = 0.f;

    float4 pa[8];
    float pb[8][4];

    // prefetch tile 0 into registers
    {
        const float* Ab = A + (size_t)bm * KK;
#pragma unroll
        for (int i = 0; i < 8; i++) {
            int fid = i * 256 + tid;
            int row = fid >> 4;
            int c4 = (fid & 15) * 4;
            pa[i] = *(const float4*)&Ab[(size_t)row * KK + c4];
        }
        const float* Bb = Bw + bn;
#pragma unroll
        for (int i = 0; i < 8; i++) {
            int fid = i * 256 + tid;
            int n = fid & 127;
            int kq = (fid >> 7) * 4;
#pragma unroll
            for (int j = 0; j < 4; j++) pb[i][j] = Bb[(size_t)(kq + j) * 256 + n];
        }
    }
    // store tile 0 -> buf0
    {
        char* buf = sm;
#pragma unroll
        for (int i = 0; i < 8; i++) {
            int fid = i * 256 + tid;
            int row = fid >> 4;
            int c4 = (fid & 15) * 4;
            float4 v = pa[i];
            float hx = __bfloat162float(__float2bfloat16(v.x));
            float hy = __bfloat162float(__float2bfloat16(v.y));
            float hz = __bfloat162float(__float2bfloat16(v.z));
            float hw = __bfloat162float(__float2bfloat16(v.w));
            uint32_t off = (uint32_t)(row * GSTR + c4) * 2;
            *(uint2*)(buf + GS_AH + off) = make_uint2(pack_bf16x2(hx, hy), pack_bf16x2(hz, hw));
            *(uint2*)(buf + GS_AL + off) =
                make_uint2(pack_bf16x2(v.x - hx, v.y - hy), pack_bf16x2(v.z - hz, v.w - hw));
        }
#pragma unroll
        for (int i = 0; i < 8; i++) {
            int fid = i * 256 + tid;
            int n = fid & 127;
            int kq = (fid >> 7) * 4;
            float b0 = pb[i][0], b1 = pb[i][1], b2 = pb[i][2], b3 = pb[i][3];
            float h0 = __bfloat162float(__float2bfloat16(b0));
            float h1 = __bfloat162float(__float2bfloat16(b1));
            float h2 = __bfloat162float(__float2bfloat16(b2));
            float h3 = __bfloat162float(__float2bfloat16(b3));
            uint32_t off = (uint32_t)(n * GSTR + kq) * 2;
            *(uint2*)(buf + GS_BH + off) = make_uint2(pack_bf16x2(h0, h1), pack_bf16x2(h2, h3));
            *(uint2*)(buf + GS_BL + off) =
                make_uint2(pack_bf16x2(b0 - h0, b1 - h1), pack_bf16x2(b2 - h2, b3 - h3));
        }
    }
    __syncthreads();

    for (int kt = 0; kt < 40; kt++) {
        char* cur = sm + (size_t)(kt & 1) * GS_BUF;
        char* nxt = sm + (size_t)((kt + 1) & 1) * GS_BUF;

        // prefetch next tile into registers (hidden behind MMA)
        if (kt < 39) {
            const float* Ab = A + (size_t)bm * KK + (kt + 1) * 64;
#pragma unroll
            for (int i = 0; i < 8; i++) {
                int fid = i * 256 + tid;
                int row = fid >> 4;
                int c4 = (fid & 15) * 4;
                pa[i] = *(const float4*)&Ab[(size_t)row * KK + c4];
            }
            const float* Bb = Bw + (size_t)((kt + 1) * 64) * 256 + bn;
#pragma unroll
            for (int i = 0; i < 8; i++) {
                int fid = i * 256 + tid;
                int n = fid & 127;
                int kq = (fid >> 7) * 4;
#pragma unroll
                for (int j = 0; j < 4; j++) pb[i][j] = Bb[(size_t)(kq + j) * 256 + n];
            }
        }

        // ---- compute from cur ----
#pragma unroll
        for (int kk = 0; kk < 4; kk++) {
            int kc = kk * 16 + (lane & 3) * 2;
            uint32_t ah[4][4], al[4][4];
#pragma unroll
            for (int mt = 0; mt < 4; mt++) {
                int r = wm + mt * 16 + (lane >> 2);
                uint32_t o00 = (uint32_t)(r * GSTR + kc) * 2;
                uint32_t o10 = (uint32_t)((r + 8) * GSTR + kc) * 2;
                ah[mt][0] = *(const uint32_t*)(cur + GS_AH + o00);
                ah[mt][1] = *(const uint32_t*)(cur + GS_AH + o10);
                ah[mt][2] = *(const uint32_t*)(cur + GS_AH + o00 + 16);
                ah[mt][3] = *(const uint32_t*)(cur + GS_AH + o10 + 16);
                al[mt][0] = *(const uint32_t*)(cur + GS_AL + o00);
                al[mt][1] = *(const uint32_t*)(cur + GS_AL + o10);
                al[mt][2] = *(const uint32_t*)(cur + GS_AL + o00 + 16);
                al[mt][3] = *(const uint32_t*)(cur + GS_AL + o10 + 16);
            }
            uint32_t bh[4][2], bl[4][2];
#pragma unroll
            for (int nt = 0; nt < 4; nt++) {
                int n = wn + nt * 8 + (lane >> 2);
                uint32_t o = (uint32_t)(n * GSTR + kc) * 2;
                bh[nt][0] = *(const uint32_t*)(cur + GS_BH + o);
                bh[nt][1] = *(const uint32_t*)(cur + GS_BH + o + 16);
                bl[nt][0] = *(const uint32_t*)(cur + GS_BL + o);
                bl[nt][1] = *(const uint32_t*)(cur + GS_BL + o + 16);
            }
#pragma unroll
            for (int mt = 0; mt < 4; mt++)
#pragma unroll
                for (int nt = 0; nt < 4; nt++) {
                    mma_bf16(acc[mt][nt], ah[mt], bh[nt]);
                    mma_bf16(acc[mt][nt], ah[mt], bl[nt]);
                    mma_bf16(acc[mt][nt], al[mt], bh[nt]);
                }
        }

        // ---- store next tile (regs ready; LDG latency hidden by MMAs) ----
        if (kt < 39) {
#pragma unroll
            for (int i = 0; i < 8; i++) {
                int fid = i * 256 + tid;
                int row = fid >> 4;
                int c4 = (fid & 15) * 4;
                float4 v = pa[i];
                float hx = __bfloat162float(__float2bfloat16(v.x));
                float hy = __bfloat162float(__float2bfloat16(v.y));
                float hz = __bfloat162float(__float2bfloat16(v.z));
                float hw = __bfloat162float(__float2bfloat16(v.w));
                uint32_t off = (uint32_t)(row * GSTR + c4) * 2;
                *(uint2*)(nxt + GS_AH + off) =
                    make_uint2(pack_bf16x2(hx, hy), pack_bf16x2(hz, hw));
                *(uint2*)(nxt + GS_AL + off) =
                    make_uint2(pack_bf16x2(v.x - hx, v.y - hy), pack_bf16x2(v.z - hz, v.w - hw));
            }
#pragma unroll
            for (int i = 0; i < 8; i++) {
                int fid = i * 256 + tid;
                int n = fid & 127;
                int kq = (fid >> 7) * 4;
                float b0 = pb[i][0], b1 = pb[i][1], b2 = pb[i][2], b3 = pb[i][3];
                float h0 = __bfloat162float(__float2bfloat16(b0));
                float h1 = __bfloat162float(__float2bfloat16(b1));
                float h2 = __bfloat162float(__float2bfloat16(b2));
                float h3 = __bfloat162float(__float2bfloat16(b3));
                uint32_t off = (uint32_t)(n * GSTR + kq) * 2;
                *(uint2*)(nxt + GS_BH + off) =
                    make_uint2(pack_bf16x2(h0, h1), pack_bf16x2(h2, h3));
                *(uint2*)(nxt + GS_BL + off) =
                    make_uint2(pack_bf16x2(b0 - h0, b1 - h1), pack_bf16x2(b2 - h2, b3 - h3));
            }
            __syncthreads();
        }
    }
#pragma unroll
    for (int mt = 0; mt < 4; mt++) {
        int r = bm + wm + mt * 16 + (lane >> 2);
#pragma unroll
        for (int nt = 0; nt < 4; nt++) {
            int c = bn + wn + nt * 8 + (lane & 3) * 2;
            float bx = bias[c], by = bias[c + 1];
            *(float2*)&g_f1[(size_t)r * 256 + c] =
                make_float2(acc[mt][nt][0] + bx, acc[mt][nt][1] + by);
            *(float2*)&g_f1[(size_t)(r + 8) * 256 + c] =
                make_float2(acc[mt][nt][2] + bx, acc[mt][nt][3] + by);
        }
    }
}

// -------- fused LN1+leaky + GEMM2 + LN2+leaky  (16 rows/block, 256 thr, 4 out/thr) ----
__global__ void __launch_bounds__(256) k_l2f(const float* __restrict__ g1,
                                             const float* __restrict__ b1,
                                             const float* __restrict__ W,
                                             const float* __restrict__ b2,
                                             const float* __restrict__ gg,
                                             const float* __restrict__ bb) {
    __shared__ float xs[16][264];
    int tid = threadIdx.x;
    int r = tid >> 4;      // 0..15
    int cg = tid & 15;     // 0..15
    size_t row = (size_t)(blockIdx.x * 16 + r);
    const float4* f1v = (const float4*)&g_f1[row * 256];
    float4 v[4];
    float s = 0.f, q = 0.f;
#pragma unroll
    for (int i = 0; i < 4; i++) {
        v[i] = f1v[cg * 4 + i];
        s += v[i].x + v[i].y + v[i].z + v[i].w;
        q += v[i].x * v[i].x + v[i].y * v[i].y + v[i].z * v[i].z + v[i].w * v[i].w;
    }
#pragma unroll
    for (int o = 8; o; o >>= 1) {
        s += __shfl_xor_sync(0xffffffffu, s, o);
        q += __shfl_xor_sync(0xffffffffu, q, o);
    }
    float mu = s * (1.f / 256.f);
    float var = q * (1.f / 256.f) - mu * mu;
    float rs = rsqrtf(var + 1e-5f);
#pragma unroll
    for (int i = 0; i < 4; i++) {
        int c0 = cg * 16 + i * 4;
        float4 gv = *(const float4*)&g1[c0];
        float4 bv = *(const float4*)&b1[c0];
        xs[r][c0 + 0] = lrelu((v[i].x - mu) * rs * gv.x + bv.x, 0.01f);
        xs[r][c0 + 1] = lrelu((v[i].y - mu) * rs * gv.y + bv.y, 0.01f);
        xs[r][c0 + 2] = lrelu((v[i].z - mu) * rs * gv.z + bv.z, 0.01f);
        xs[r][c0 + 3] = lrelu((v[i].w - mu) * rs * gv.w + bv.w, 0.01f);
    }
    __syncthreads();
    int c = cg * 4;
    float4 acc = *(const float4*)&b2[c];
    const float4* W4 = (const float4*)W;
#pragma unroll 8
    for (int k = 0; k < 256; k++) {
        float xv = xs[r][k];
        float4 w = W4[k * 16 + cg];
        acc.x += xv * w.x; acc.y += xv * w.y; acc.z += xv * w.z; acc.w += xv * w.w;
    }
    float s2 = acc.x + acc.y + acc.z + acc.w;
    float q2 = acc.x * acc.x + acc.y * acc.y + acc.z * acc.z + acc.w * acc.w;
#pragma unroll
    for (int o = 8; o; o >>= 1) {
        s2 += __shfl_xor_sync(0xffffffffu, s2, o);
        q2 += __shfl_xor_sync(0xffffffffu, q2, o);
    }
    float mu2 = s2 * (1.f / 64.f);
    float var2 = q2 * (1.f / 64.f) - mu2 * mu2;
    float rs2 = rsqrtf(var2 + 1e-5f);
    float4 gv = *(const float4*)&gg[c];
    float4 bv = *(const float4*)&bb[c];
    float4 o4;
    o4.x = lrelu((acc.x - mu2) * rs2 * gv.x + bv.x, 0.01f);
    o4.y = lrelu((acc.y - mu2) * rs2 * gv.y + bv.y, 0.01f);
    o4.z = lrelu((acc.z - mu2) * rs2 * gv.z + bv.z, 0.01f);
    o4.w = lrelu((acc.w - mu2) * rs2 * gv.w + bv.w, 0.01f);
    *(float4*)&g_f2[row * 64 + c] = o4;
}

// -------- GEMM3 [*,64]->[*,8] fused with LN3 + leaky --------
__global__ void k_l3(const float* __restrict__ W, const float* __restrict__ b3,
                     const float* __restrict__ gg, const float* __restrict__ bb) {
    __shared__ float xs[32][65];
    __shared__ float w3[512];
    int tid = threadIdx.x;
#pragma unroll
    for (int i = 0; i < 2; i++) w3[i * 256 + tid] = W[i * 256 + tid];
#pragma unroll
    for (int i = 0; i < 2; i++) {
        int fid = i * 256 + tid;
        int rr = fid / 16, cc = (fid % 16) * 4;
        float4 v = *(const float4*)&g_f2[(blockIdx.x * 32 + rr) * 64 + cc];
        xs[rr][cc + 0] = v.x; xs[rr][cc + 1] = v.y; xs[rr][cc + 2] = v.z; xs[rr][cc + 3] = v.w;
    }
    __syncthreads();
    int r = tid / 8, c = tid % 8;
    float acc = b3[c];
#pragma unroll 8
    for (int k = 0; k < 64; k++) acc += xs[r][k] * w3[k * 8 + c];
    float s = acc, q = acc * acc;
#pragma unroll
    for (int o = 4; o; o >>= 1) {
        s += __shfl_xor_sync(0xffffffffu, s, o);
        q += __shfl_xor_sync(0xffffffffu, q, o);
    }
    float mu = s * (1.f / 8.f);
    float var = q * (1.f / 8.f) - mu * mu;
    float y = (acc - mu) * rsqrtf(var + 1e-5f) * gg[c] + bb[c];
    g_f3[(blockIdx.x * 32 + r) * 8 + c] = lrelu(y, 0.01f);
}

// -------- flatten: [B,1024]@[1024,32] + LN4 + leaky  (512 threads) --------
__global__ void k_flat(const float* __restrict__ W, const float* __restrict__ fb,
                       const float* __restrict__ gg, const float* __restrict__ bb) {
    __shared__ float xs[1024];
    __shared__ float part[512];
    int b = blockIdx.x, tid = threadIdx.x;   // 512 threads
    if (tid < 256) {
        *(float4*)&xs[tid * 4] = *(const float4*)&g_f3[b * 1024 + tid * 4];
    }
    __syncthreads();
    int c = tid & 31, qr = tid >> 5;        // 16 chunks of 64 k
    float acc = 0.f;
#pragma unroll 8
    for (int k = qr * 64; k < qr * 64 + 64; k++) acc += xs[k] * W[k * 32 + c];
    part[tid] = acc;
    __syncthreads();
    if (tid < 32) {
        float a = fb[tid];
#pragma unroll
        for (int j = 0; j < 16; j++) a += part[tid + 32 * j];
        float s = a, q = a * a;
#pragma unroll
        for (int o = 16; o; o >>= 1) {
            s += __shfl_xor_sync(0xffffffffu, s, o);
            q += __shfl_xor_sync(0xffffffffu, q, o);
        }
        float mu = s * (1.f / 32.f);
        float var = q * (1.f / 32.f) - mu * mu;
        g_xf[b * 32 + tid] = lrelu((a - mu) * rsqrtf(var + 1e-5f) * gg[tid] + bb[tid], 0.01f);
    }
}

// -------- final --------
__global__ void k_final(const float* __restrict__ oneh, const float* __restrict__ W,
                        const float* __restrict__ ob, float* __restrict__ out) {
    int tid = threadIdx.x;
    if (tid >= 128) return;
    int b = tid >> 1, o = tid & 1;
    float acc = ob[o];
    float cnt = fmaxf(g_pooled[b * 8 + 4], 1.f);
    float ic = 1.f / cnt;
#pragma unroll
    for (int j = 0; j < 4; j++) acc += g_pooled[b * 8 + j] * ic * W[j * 2 + o];
#pragma unroll
    for (int j = 0; j < 32; j++) acc += g_xf[b * 32 + j] * W[(4 + j) * 2 + o];
#pragma unroll
    for (int j = 0; j < 20; j++) acc += oneh[b * 20 + j] * W[(36 + j) * 2 + o];
    out[b * 2 + o] = acc;
}

extern "C" void kernel_launch(void* const* d_in, const int* in_sizes, int n_in,
                              void* d_out, int out_size) {
    const float *x, *features, *one_hot, *W_l, *b_l, *W_r, *b_r, *att, *conv_b, *jk_W, *jk_b;
    const float *l1_W, *l1_b, *ln1_g, *ln1_b, *l2_W, *l2_b, *ln2_g, *ln2_b;
    const float *l3_W, *l3_b, *ln3_g, *ln3_b, *fl_W, *fl_b, *ln4_g, *ln4_b, *out_W, *out_b;
    const int *edge_index, *batch;

    if (in_sizes[1] == 2 * EE) {
        x = (const float*)d_in[0]; edge_index = (const int*)d_in[1]; batch = (const int*)d_in[2];
        features = (const float*)d_in[3]; one_hot = (const float*)d_in[4];
        W_l = (const float*)d_in[5]; b_l = (const float*)d_in[6];
        W_r = (const float*)d_in[7]; b_r = (const float*)d_in[8];
        att = (const float*)d_in[9]; conv_b = (const float*)d_in[10];
        jk_W = (const float*)d_in[11]; jk_b = (const float*)d_in[12];
        l1_W = (const float*)d_in[13]; l1_b = (const float*)d_in[14];
        ln1_g = (const float*)d_in[15]; ln1_b = (const float*)d_in[16];
        l2_W = (const float*)d_in[17]; l2_b = (const float*)d_in[18];
        ln2_g = (const float*)d_in[19]; ln2_b = (const float*)d_in[20];
        l3_W = (const float*)d_in[21]; l3_b = (const float*)d_in[22];
        ln3_g = (const float*)d_in[23]; ln3_b = (const float*)d_in[24];
        fl_W = (const float*)d_in[25]; fl_b = (const float*)d_in[26];
        ln4_g = (const float*)d_in[27]; ln4_b = (const float*)d_in[28];
        out_W = (const float*)d_in[29]; out_b = (const float*)d_in[30];
    } else {
        x = (const float*)d_in[0]; features = (const float*)d_in[1]; one_hot = (const float*)d_in[2];
        W_l = (const float*)d_in[3]; b_l = (const float*)d_in[4];
        W_r = (const float*)d_in[5]; b_r = (const float*)d_in[6];
        att = (const float*)d_in[7]; conv_b = (const float*)d_in[8];
        jk_W = (const float*)d_in[9]; jk_b = (const float*)d_in[10];
        l1_W = (const float*)d_in[11]; l1_b = (const float*)d_in[12];
        ln1_g = (const float*)d_in[13]; ln1_b = (const float*)d_in[14];
        l2_W = (const float*)d_in[15]; l2_b = (const float*)d_in[16];
        ln2_g = (const float*)d_in[17]; ln2_b = (const float*)d_in[18];
        l3_W = (const float*)d_in[19]; l3_b = (const float*)d_in[20];
        ln3_g = (const float*)d_in[21]; ln3_b = (const float*)d_in[22];
        fl_W = (const float*)d_in[23]; fl_b = (const float*)d_in[24];
        ln4_g = (const float*)d_in[25]; ln4_b = (const float*)d_in[26];
        out_W = (const float*)d_in[27]; out_b = (const float*)d_in[28];
        edge_index = (const int*)d_in[29]; batch = (const int*)d_in[30];
    }

    static cudaStream_t s2 = nullptr, s3 = nullptr;
    static cudaEvent_t evF = nullptr, evJ = nullptr, evZ = nullptr;
    if (s2 == nullptr) {
        cudaStreamCreateWithFlags(&s2, cudaStreamNonBlocking);
        cudaStreamCreateWithFlags(&s3, cudaStreamNonBlocking);
        cudaEventCreateWithFlags(&evF, cudaEventDisableTiming);
        cudaEventCreateWithFlags(&evJ, cudaEventDisableTiming);
        cudaEventCreateWithFlags(&evZ, cudaEventDisableTiming);
        cudaFuncSetAttribute(k_gemm1_mma, cudaFuncAttributeMaxDynamicSharedMemorySize, GS_TOTAL);
    }

    // fork: MLP chain on s2, pooled-zero on s3, GNN chain on default stream
    cudaEventRecord(evF, 0);
    cudaStreamWaitEvent(s2, evF, 0);
    cudaStreamWaitEvent(s3, evF, 0);

    k_gemm1_mma<<<dim3(2, 64), 256, GS_TOTAL, s2>>>(features, l1_W, l1_b);
    k_l2f<<<MM / 16, 256, 0, s2>>>(ln1_g, ln1_b, l2_W, l2_b, ln2_g, ln2_b);
    k_l3<<<MM / 32, 256, 0, s2>>>(l3_W, l3_b, ln3_g, ln3_b);
    k_flat<<<BB, 512, 0, s2>>>(fl_W, fl_b, ln4_g, ln4_b);
    cudaEventRecord(evJ, s2);

    k_zero<<<1, 128, 0, s3>>>();
    cudaEventRecord(evZ, s3);

    // GNN chain: xlxr initializes g_aggh with self-loop term; edge REDs on top
    k_xlxr<<<(NN + 511) / 512, 128>>>(x, W_l, W_r, b_l, b_r, att);
    k_edge8<<<(EE / 8 + 127) / 128, 128>>>(edge_index, att);
    cudaStreamWaitEvent(0, evZ, 0);
    k_node<<<(NN + 255) / 256, 256>>>(batch, conv_b, jk_W, jk_b);

    // join
    cudaStreamWaitEvent(0, evJ, 0);
    k_final<<<1, 128>>>(one_hot, out_W, out_b, (float*)d_out);
}